// round 10
// baseline (speedup 1.0000x reference)
#include <cuda_runtime.h>
#include <cuda_bf16.h>
#include <math.h>
#include <stdint.h>

// Problem dims (fixed)
#define TT 128
#define BB 256
#define VV 256
#define NN 1024
#define TB (TT*BB)   // 32768

// ---------------------------------------------------------------------------
// Device-global scratch (no allocation allowed in kernel_launch)
__device__ float g_xproj[(size_t)TB * NN];                  // x @ w_x + bias (fp32)
__device__ __nv_bfloat16 g_whT[(size_t)NN * NN];            // w_h^T  bf16 [N=1024,K=1024]
__device__ __nv_bfloat16 g_wxT[(size_t)NN * VV];            // w_x^T  bf16 [N=1024,K=256]
__device__ __nv_bfloat16 g_woT[(size_t)VV * NN];            // w_out^T bf16 [N=256,K=1024]
__device__ __nv_bfloat16 g_xbf[(size_t)TB * VV];            // X bf16 [32768,256]
__device__ __nv_bfloat16 g_hbf[(size_t)(TT + 1) * BB * NN]; // bf16 h states (slice t = h_t)
__device__ unsigned g_bar[TT * 8 * 4];                      // per-(step, m-group, k-quarter)

// ===========================================================================
// Helpers
// ===========================================================================
__device__ __forceinline__ void mma16816(
    float& c0, float& c1, float& c2, float& c3,
    uint32_t a0, uint32_t a1, uint32_t a2, uint32_t a3,
    uint32_t b0, uint32_t b1)
{
    asm volatile(
        "mma.sync.aligned.m16n8k16.row.col.f32.bf16.bf16.f32 "
        "{%0,%1,%2,%3}, {%4,%5,%6,%7}, {%8,%9}, {%0,%1,%2,%3};"
        : "+f"(c0), "+f"(c1), "+f"(c2), "+f"(c3)
        : "r"(a0), "r"(a1), "r"(a2), "r"(a3), "r"(b0), "r"(b1));
}

__device__ __forceinline__ void cp16(void* smem_dst, const void* gsrc) {
    uint32_t d;
    asm("{ .reg .u64 t; cvta.to.shared.u64 t, %1; cvt.u32.u64 %0, t; }" : "=r"(d) : "l"(smem_dst));
    asm volatile("cp.async.cg.shared.global [%0], [%1], 16;\n" :: "r"(d), "l"(gsrc));
}
#define CP_COMMIT() asm volatile("cp.async.commit_group;\n" ::: "memory")
#define CP_WAIT(n)  asm volatile("cp.async.wait_group %0;\n" :: "n"(n) : "memory")

__device__ __forceinline__ float tanh_fast(float x) {
    float y;
    asm("tanh.approx.f32 %0, %1;" : "=f"(y) : "f"(x));
    return y;
}

#define PAD 40   // smem row pitch in bf16 for GEMM tiles

// ===========================================================================
// Persistent RNN recurrence kernel.
// Grid (16, 8) = 128 CTAs co-resident, 128 threads each.
// CTA (bx,by): rows m0=by*32, cols n0=bx*64.
// Persistent smem: B slice whT[n0:n0+64, :] (132 KB).
// Per step: A tile h_t[m0:m0+32, :1024] (66 KB), X tile double-buffered.
// Sub-barrier per (h-slice, m-group, k-quarter): consumer's chunk q waits only
// on the 4 producer CTAs bx in [4q, 4q+4) -> loads overlap producer skew.
// ===========================================================================
#define BS_PITCH 1032                      // bf16
#define AS_PITCH 1032                      // bf16
#define XS_PITCH 68                        // fp32
#define SMEM_BS (64 * BS_PITCH * 2)        // 132096
#define SMEM_AS (32 * AS_PITCH * 2)        // 66048
#define SMEM_XS (2 * 32 * XS_PITCH * 4)    // 17408
#define RNN_SMEM (SMEM_BS + SMEM_AS + SMEM_XS)   // 215552

__global__ __launch_bounds__(128, 1) void rnn_persist(
    __nv_bfloat16* __restrict__ hbf,          // (TT+1) slices of [256,1024]
    const __nv_bfloat16* __restrict__ whT,    // [1024,1024]
    const float* __restrict__ xproj,          // [TT,256,1024] fp32
    unsigned* __restrict__ bar)
{
    extern __shared__ char smem_raw[];
    __nv_bfloat16* Bs = (__nv_bfloat16*)smem_raw;                   // [64][1032]
    __nv_bfloat16* As = (__nv_bfloat16*)(smem_raw + SMEM_BS);       // [32][1032]
    float*         Xs = (float*)(smem_raw + SMEM_BS + SMEM_AS);     // [2][32][68]

    const int tid = threadIdx.x;
    const int wid = tid >> 5;
    const int lane = tid & 31;
    const int g  = lane >> 2;    // 0..7
    const int tg = lane & 3;     // 0..3
    const int warpM = wid & 1;   // 2 x 16 rows
    const int warpN = wid >> 1;  // 2 x 32 cols
    const int bx = blockIdx.x;
    const int by = blockIdx.y;
    const int n0 = bx * 64;
    const int m0 = by * 32;
    const int myq = bx >> 2;     // which k-quarter this CTA's output lands in

    // ---- persistent B slice load: whT rows n0..n0+63, K=1024 ----
    #pragma unroll
    for (int i = 0; i < 64; i++) {
        int u = tid + i * 128;
        int row = u >> 7;        // 0..63
        int seg = u & 127;       // 16B units
        cp16((char*)Bs + row * (BS_PITCH * 2) + seg * 16,
             whT + (size_t)(n0 + row) * NN + seg * 8);
    }
    CP_COMMIT();

    // ---- t = 0: h_1 = tanh(xproj_0) for this (m,n) tile ----
    {
        const float* xp0 = xproj;
        __nv_bfloat16* h1 = hbf + (size_t)1 * BB * NN;
        #pragma unroll
        for (int i = 0; i < 16; i++) {
            int u = tid + i * 128;
            int r = m0 + (u >> 6);
            int cl = n0 + (u & 63);
            h1[(size_t)r * NN + cl] = __float2bfloat16(tanh_fast(xp0[(size_t)r * NN + cl]));
        }
    }
    __threadfence();
    __syncthreads();
    if (tid == 0) atomicAdd(&bar[(0 * 8 + by) * 4 + myq], 1u);   // h_1 quarter ready

    CP_WAIT(0);           // B slice resident; no cp groups pending
    __syncthreads();

    // prefetch X tile for t=1 into Xs[1]  -> 1 group pending entering the loop
    {
        const float* xp1 = xproj + (size_t)1 * BB * NN;
        float* Xd = Xs + (size_t)(1 & 1) * 32 * XS_PITCH;
        #pragma unroll
        for (int i = 0; i < 4; i++) {
            int u = tid + i * 128;
            int r = u >> 4;
            int sg = u & 15;
            cp16((char*)Xd + r * (XS_PITCH * 4) + sg * 16,
                 xp1 + (size_t)(m0 + r) * NN + n0 + sg * 4);
        }
        CP_COMMIT();
    }

    // ---- steps t = 1 .. 127: h_{t+1} = tanh(xproj_t + h_t @ w_h) ----
    // Invariant entering step t: exactly one cp.async group pending = X(t).
    #pragma unroll 1
    for (int t = 1; t < TT; t++) {
        const __nv_bfloat16* At = hbf + (size_t)t * BB * NN + (size_t)m0 * NN;
        __nv_bfloat16* hn = hbf + (size_t)(t + 1) * BB * NN;
        const unsigned* bwait = &bar[((t - 1) * 8 + by) * 4];   // h_t readiness

        float acc[4][4];
        #pragma unroll
        for (int ni = 0; ni < 4; ni++)
            #pragma unroll
            for (int e = 0; e < 4; e++) acc[ni][e] = 0.0f;

        const int ra = warpM * 16 + g;

        // wait for h_t quarter q, then issue A-chunk q (256 k-cols, 16KB)
#define SUBWAIT(Q)                                                              \
        if (tid == 0) {                                                         \
            volatile const unsigned* bq = bwait + (Q);                          \
            while (*bq < 4u) __nanosleep(32);                                   \
        }                                                                       \
        __syncthreads();

#define ISSUE_A(C)                                                              \
        _Pragma("unroll")                                                       \
        for (int i = 0; i < 8; i++) {                                           \
            int u = tid + i * 128;                                              \
            int r = u >> 5;                                                     \
            int sg = u & 31;                                                    \
            cp16((char*)As + r * (AS_PITCH * 2) + (C) * 512 + sg * 16,          \
                 At + (size_t)r * NN + (C) * 256 + sg * 8);                     \
        }                                                                       \
        CP_COMMIT();

#define DO_CHUNK(C, W)                                                          \
        CP_WAIT(W);                                                             \
        __syncthreads();                                                        \
        _Pragma("unroll")                                                       \
        for (int kk = 0; kk < 256; kk += 16) {                                  \
            const int k = (C) * 256 + kk + 2 * tg;                              \
            uint32_t a0 = *(const uint32_t*)&As[(size_t)ra * AS_PITCH + k];     \
            uint32_t a1 = *(const uint32_t*)&As[(size_t)(ra + 8) * AS_PITCH + k];\
            uint32_t a2 = *(const uint32_t*)&As[(size_t)ra * AS_PITCH + k + 8]; \
            uint32_t a3 = *(const uint32_t*)&As[(size_t)(ra + 8) * AS_PITCH + k + 8];\
            _Pragma("unroll")                                                   \
            for (int ni = 0; ni < 4; ni++) {                                    \
                const int bn = warpN * 32 + ni * 8 + g;                         \
                uint32_t b0 = *(const uint32_t*)&Bs[(size_t)bn * BS_PITCH + k]; \
                uint32_t b1 = *(const uint32_t*)&Bs[(size_t)bn * BS_PITCH + k + 8];\
                mma16816(acc[ni][0], acc[ni][1], acc[ni][2], acc[ni][3],        \
                         a0, a1, a2, a3, b0, b1);                               \
            }                                                                   \
        }

        SUBWAIT(0) ISSUE_A(0)        // pending: X(t), A0
        SUBWAIT(1) ISSUE_A(1)        // pending: X(t), A0, A1
        DO_CHUNK(0, 1)               // completes X(t), A0
        SUBWAIT(2) ISSUE_A(2)        // pending: A1, A2
        DO_CHUNK(1, 1)               // completes A1
        SUBWAIT(3) ISSUE_A(3)        // pending: A2, A3
        {   // prefetch X(t+1) (dummy re-fetch at last step keeps invariant)
            const int tn = (t + 1 < TT) ? (t + 1) : t;
            const float* xpn = xproj + (size_t)tn * BB * NN;
            float* Xd = Xs + (size_t)((t + 1) & 1) * 32 * XS_PITCH;
            #pragma unroll
            for (int i = 0; i < 4; i++) {
                int u = tid + i * 128;
                int r = u >> 4;
                int sg = u & 15;
                cp16((char*)Xd + r * (XS_PITCH * 4) + sg * 16,
                     xpn + (size_t)(m0 + r) * NN + n0 + sg * 4);
            }
            CP_COMMIT();             // pending: A2, A3, X(t+1)
        }
        DO_CHUNK(2, 2)               // completes A2
        DO_CHUNK(3, 1)               // completes A3; X(t+1) pending
#undef SUBWAIT
#undef ISSUE_A
#undef DO_CHUNK

        // epilogue: tanh(acc + Xs[t&1]) -> bf16 h_{t+1}
        const float* Xr = Xs + (size_t)(t & 1) * 32 * XS_PITCH;
        #pragma unroll
        for (int ni = 0; ni < 4; ni++) {
            const int lc = warpN * 32 + ni * 8 + 2 * tg;    // local col 0..63
            #pragma unroll
            for (int h = 0; h < 2; h++) {
                const int lr = warpM * 16 + g + h * 8;      // local row 0..31
                const float2 xv = *(const float2*)&Xr[lr * XS_PITCH + lc];
                float v0 = tanh_fast(acc[ni][2 * h + 0] + xv.x);
                float v1 = tanh_fast(acc[ni][2 * h + 1] + xv.y);
                *(__nv_bfloat162*)(hn + (size_t)(m0 + lr) * NN + n0 + lc) =
                    __floats2bfloat162_rn(v0, v1);
            }
        }

        // signal h_{t+1} quarter ready (skip after last step)
        if (t < TT - 1) {
            __threadfence();
            __syncthreads();
            if (tid == 0) atomicAdd(&bar[(t * 8 + by) * 4 + myq], 1u);
        }
    }
}

// ===========================================================================
// Generic bf16 HMMA GEMM (xproj only): C[M,N] = A[M,K] @ BT[N,K]^T (+bias).
// CTA 64x128, grid(N/128, M/64). K multiple of 32.
// ===========================================================================
__global__ __launch_bounds__(256) void hgemm(
    const __nv_bfloat16* __restrict__ A,   // [M,K] row-major
    const __nv_bfloat16* __restrict__ BT,  // [N,K] row-major
    float* __restrict__ C,
    const float* __restrict__ bias,        // len N
    int K, int ldc)
{
    __shared__ __nv_bfloat16 As[2][64][PAD];
    __shared__ __nv_bfloat16 Bs[2][128][PAD];

    const int tid = threadIdx.x;
    const int wid = tid >> 5;
    const int lane = tid & 31;
    const int g  = lane >> 2;
    const int tg = lane & 3;
    const int warpM = wid & 1;
    const int warpN = wid >> 1;
    const int n0 = blockIdx.x * 128;
    const int m0 = blockIdx.y * 64;

    const __nv_bfloat16* Ab = A + (size_t)m0 * K;
    const __nv_bfloat16* Bb = BT + (size_t)n0 * K;

    const int ar  = tid >> 2;
    const int seg = tid & 3;

    float acc[2][4][4];
    #pragma unroll
    for (int mi = 0; mi < 2; mi++)
        #pragma unroll
        for (int ni = 0; ni < 4; ni++)
            #pragma unroll
            for (int e = 0; e < 4; e++) acc[mi][ni][e] = 0.0f;

    cp16(&As[0][ar][seg * 8], Ab + (size_t)ar * K + seg * 8);
    #pragma unroll
    for (int i = 0; i < 2; i++)
        cp16(&Bs[0][ar + i * 64][seg * 8], Bb + (size_t)(ar + i * 64) * K + seg * 8);
    CP_COMMIT();

    const int NK = K / 32;
    #pragma unroll 1
    for (int c = 0; c < NK; c++) {
        const int s = c & 1;
        if (c + 1 < NK) {
            const int sn = (c + 1) & 1;
            const int k0 = (c + 1) * 32;
            cp16(&As[sn][ar][seg * 8], Ab + (size_t)ar * K + k0 + seg * 8);
            #pragma unroll
            for (int i = 0; i < 2; i++)
                cp16(&Bs[sn][ar + i * 64][seg * 8],
                     Bb + (size_t)(ar + i * 64) * K + k0 + seg * 8);
            CP_COMMIT();
            CP_WAIT(1);
        } else {
            CP_WAIT(0);
        }
        __syncthreads();

        #pragma unroll
        for (int kk = 0; kk < 32; kk += 16) {
            uint32_t af[2][4];
            #pragma unroll
            for (int mi = 0; mi < 2; mi++) {
                const int r = warpM * 32 + mi * 16 + g;
                af[mi][0] = *(const uint32_t*)&As[s][r][kk + 2 * tg];
                af[mi][1] = *(const uint32_t*)&As[s][r + 8][kk + 2 * tg];
                af[mi][2] = *(const uint32_t*)&As[s][r][kk + 2 * tg + 8];
                af[mi][3] = *(const uint32_t*)&As[s][r + 8][kk + 2 * tg + 8];
            }
            #pragma unroll
            for (int ni = 0; ni < 4; ni++) {
                const int n = warpN * 32 + ni * 8 + g;
                uint32_t b0 = *(const uint32_t*)&Bs[s][n][kk + 2 * tg];
                uint32_t b1 = *(const uint32_t*)&Bs[s][n][kk + 2 * tg + 8];
                #pragma unroll
                for (int mi = 0; mi < 2; mi++)
                    mma16816(acc[mi][ni][0], acc[mi][ni][1], acc[mi][ni][2], acc[mi][ni][3],
                             af[mi][0], af[mi][1], af[mi][2], af[mi][3], b0, b1);
            }
        }
        __syncthreads();
    }

    #pragma unroll
    for (int mi = 0; mi < 2; mi++) {
        const int r0 = m0 + warpM * 32 + mi * 16 + g;
        #pragma unroll
        for (int ni = 0; ni < 4; ni++) {
            const int col = n0 + warpN * 32 + ni * 8 + 2 * tg;
            const float2 bv = *(const float2*)(bias + col);
            #pragma unroll
            for (int h = 0; h < 2; h++) {
                const int r = r0 + h * 8;
                *(float2*)(C + (size_t)r * ldc + col) =
                    make_float2(acc[mi][ni][2 * h + 0] + bv.x,
                                acc[mi][ni][2 * h + 1] + bv.y);
            }
        }
    }
}

// ===========================================================================
// Fused logits + loss kernel.
// C-tile: 64 rows x 256 cols (full V). grid = TB/64 = 512 CTAs, 256 threads.
// ===========================================================================
#define LL_LS_PITCH 264   // fp32 row pitch for staged logits
#define LL_SMEM 67584

__global__ __launch_bounds__(256) void logits_loss(
    const __nv_bfloat16* __restrict__ A,    // h states [TB,1024] bf16
    const __nv_bfloat16* __restrict__ BT,   // woT [256,1024] bf16
    const float* __restrict__ labels,       // [TB,256] fp32
    const float* __restrict__ obias,        // [256]
    float* __restrict__ out)
{
    extern __shared__ char sm[];
    __nv_bfloat16 (*As)[64][PAD] = (__nv_bfloat16 (*)[64][PAD])sm;
    __nv_bfloat16 (*Bs)[256][PAD] = (__nv_bfloat16 (*)[256][PAD])(sm + 2 * 64 * PAD * 2);
    float* Ls = (float*)sm;   // reused after mainloop

    const int tid = threadIdx.x;
    const int wid = tid >> 5;
    const int lane = tid & 31;
    const int g  = lane >> 2;
    const int tg = lane & 3;
    const int warpM = wid & 3;    // 4 x 16 rows
    const int warpN = wid >> 2;   // 2 x 128 cols
    const int m0 = blockIdx.x * 64;

    const __nv_bfloat16* Ab = A + (size_t)m0 * NN;

    const int ar  = tid >> 2;    // 0..63
    const int seg = tid & 3;     // 0..3

    float acc[16][4];
    #pragma unroll
    for (int ni = 0; ni < 16; ni++)
        #pragma unroll
        for (int e = 0; e < 4; e++) acc[ni][e] = 0.0f;

    // prologue chunk 0
    cp16(&(*As)[ar][seg * 8], Ab + (size_t)ar * NN + seg * 8);
    #pragma unroll
    for (int i = 0; i < 4; i++) {
        int u = tid + i * 256;
        int br = u >> 2;
        int bs = u & 3;
        cp16(&(*Bs)[br][bs * 8], BT + (size_t)br * NN + bs * 8);
    }
    CP_COMMIT();

    const int NK = NN / 32;   // 32 chunks
    #pragma unroll 1
    for (int c = 0; c < NK; c++) {
        const int s = c & 1;
        if (c + 1 < NK) {
            const int sn = (c + 1) & 1;
            const int k0 = (c + 1) * 32;
            cp16(&As[sn][0][0] + (size_t)ar * PAD + seg * 8, Ab + (size_t)ar * NN + k0 + seg * 8);
            #pragma unroll
            for (int i = 0; i < 4; i++) {
                int u = tid + i * 256;
                int br = u >> 2;
                int bs = u & 3;
                cp16(&Bs[sn][0][0] + (size_t)br * PAD + bs * 8,
                     BT + (size_t)br * NN + k0 + bs * 8);
            }
            CP_COMMIT();
            CP_WAIT(1);
        } else {
            CP_WAIT(0);
        }
        __syncthreads();

        #pragma unroll
        for (int kk = 0; kk < 32; kk += 16) {
            const int r = warpM * 16 + g;
            uint32_t a0 = *(const uint32_t*)&As[s][r][kk + 2 * tg];
            uint32_t a1 = *(const uint32_t*)&As[s][r + 8][kk + 2 * tg];
            uint32_t a2 = *(const uint32_t*)&As[s][r][kk + 2 * tg + 8];
            uint32_t a3 = *(const uint32_t*)&As[s][r + 8][kk + 2 * tg + 8];
            #pragma unroll
            for (int ni = 0; ni < 16; ni++) {
                const int n = warpN * 128 + ni * 8 + g;
                uint32_t b0 = *(const uint32_t*)&Bs[s][n][kk + 2 * tg];
                uint32_t b1 = *(const uint32_t*)&Bs[s][n][kk + 2 * tg + 8];
                mma16816(acc[ni][0], acc[ni][1], acc[ni][2], acc[ni][3],
                         a0, a1, a2, a3, b0, b1);
            }
        }
        __syncthreads();
    }

    // ---- stage logits (+obias) into smem ----
    #pragma unroll
    for (int ni = 0; ni < 16; ni++) {
        const int col = warpN * 128 + ni * 8 + 2 * tg;
        const float2 bv = *(const float2*)(obias + col);
        #pragma unroll
        for (int h = 0; h < 2; h++) {
            const int row = warpM * 16 + g + h * 8;
            Ls[row * LL_LS_PITCH + col]     = acc[ni][2 * h + 0] + bv.x;
            Ls[row * LL_LS_PITCH + col + 1] = acc[ni][2 * h + 1] + bv.y;
        }
    }
    __syncthreads();

    // ---- per-warp loss over 8 rows each ----
    float wloss = 0.0f;
    #pragma unroll 1
    for (int rr = 0; rr < 8; rr++) {
        const int row = wid * 8 + rr;
        const float* lr = &Ls[row * LL_LS_PITCH];
        const float* labr = labels + (size_t)(m0 + row) * VV;

        float l[8], lb[8];
        #pragma unroll
        for (int j = 0; j < 8; j++) {
            l[j]  = lr[lane + 32 * j];
            lb[j] = labr[lane + 32 * j];
        }
        float m = l[0];
        #pragma unroll
        for (int j = 1; j < 8; j++) m = fmaxf(m, l[j]);
        #pragma unroll
        for (int o = 16; o > 0; o >>= 1) m = fmaxf(m, __shfl_xor_sync(0xffffffffu, m, o));

        float se = 0.0f;
        #pragma unroll
        for (int j = 0; j < 8; j++) se += __expf(l[j] - m);
        #pragma unroll
        for (int o = 16; o > 0; o >>= 1) se += __shfl_xor_sync(0xffffffffu, se, o);
        const float lse = m + __logf(se);

        float cn = 0.0f;
        #pragma unroll
        for (int j = 0; j < 8; j++) cn += lb[j] * (l[j] - lse);
        #pragma unroll
        for (int o = 16; o > 0; o >>= 1) cn += __shfl_xor_sync(0xffffffffu, cn, o);
        wloss += cn;
    }
    if (lane == 0) atomicAdd(out, -wloss * (1.0f / (float)TB));
}

// ---------------------------------------------------------------------------
// Generic fp32 [R,Cc] -> bf16 transpose [Cc,R]
__global__ void transp_bf16(const float* __restrict__ src, __nv_bfloat16* __restrict__ dst,
                            int R, int Cc)
{
    __shared__ float t[32][33];
    const int r0 = blockIdx.x * 32, c0 = blockIdx.y * 32;
    #pragma unroll
    for (int i = 0; i < 32; i += 8)
        t[threadIdx.y + i][threadIdx.x] = src[(size_t)(r0 + threadIdx.y + i) * Cc + c0 + threadIdx.x];
    __syncthreads();
    #pragma unroll
    for (int i = 0; i < 32; i += 8)
        dst[(size_t)(c0 + threadIdx.y + i) * R + r0 + threadIdx.x] =
            __float2bfloat16(t[threadIdx.x][threadIdx.y + i]);
}

// fp32 -> bf16 convert (vectorized; count is a multiple of 4*256)
__global__ __launch_bounds__(256) void f32_to_bf16(
    const float* __restrict__ src, __nv_bfloat16* __restrict__ dst)
{
    const size_t i = (size_t)blockIdx.x * blockDim.x + threadIdx.x;
    float4 v = *(const float4*)(src + i * 4);
    __nv_bfloat162* d = (__nv_bfloat162*)(dst + i * 4);
    d[0] = __floats2bfloat162_rn(v.x, v.y);
    d[1] = __floats2bfloat162_rn(v.z, v.w);
}

__global__ void zero_out(float* out) { if (threadIdx.x == 0) out[0] = 0.0f; }
__global__ void zero_bar(unsigned* bar) {
    int i = blockIdx.x * 256 + threadIdx.x;
    if (i < TT * 8 * 4) bar[i] = 0u;
}

// ===========================================================================
extern "C" void kernel_launch(void* const* d_in, const int* in_sizes, int n_in,
                              void* d_out, int out_size)
{
    (void)in_sizes; (void)n_in; (void)out_size;
    const float* inputs  = (const float*)d_in[0]; // [T,B,V] == [TB,V]
    const float* labels  = (const float*)d_in[1]; // [TB,V]
    const float* weights = (const float*)d_in[2]; // [V+N, N]
    const float* bias    = (const float*)d_in[3]; // [N]
    const float* w_out   = (const float*)d_in[4]; // [N,V]
    const float* obias   = (const float*)d_in[5]; // [V]
    float* out = (float*)d_out;

    float *xproj;
    __nv_bfloat16 *whT, *wxT, *woT, *xbf, *hbf;
    unsigned* bar;
    cudaGetSymbolAddress((void**)&xproj,  g_xproj);
    cudaGetSymbolAddress((void**)&whT,    g_whT);
    cudaGetSymbolAddress((void**)&wxT,    g_wxT);
    cudaGetSymbolAddress((void**)&woT,    g_woT);
    cudaGetSymbolAddress((void**)&xbf,    g_xbf);
    cudaGetSymbolAddress((void**)&hbf,    g_hbf);
    cudaGetSymbolAddress((void**)&bar,    g_bar);

    const float* w_x = weights;                    // [V=256, N=1024]
    const float* w_h = weights + (size_t)VV * NN;  // [N=1024, N=1024]

    cudaFuncSetAttribute(rnn_persist, cudaFuncAttributeMaxDynamicSharedMemorySize, RNN_SMEM);
    cudaFuncSetAttribute(logits_loss, cudaFuncAttributeMaxDynamicSharedMemorySize, LL_SMEM);

    zero_out<<<1, 32>>>(out);
    zero_bar<<<16, 256>>>(bar);
    transp_bf16<<<dim3(NN / 32, NN / 32), dim3(32, 8)>>>(w_h, whT, NN, NN);
    transp_bf16<<<dim3(VV / 32, NN / 32), dim3(32, 8)>>>(w_x, wxT, VV, NN);
    transp_bf16<<<dim3(NN / 32, VV / 32), dim3(32, 8)>>>(w_out, woT, NN, VV);
    f32_to_bf16<<<((size_t)TB * VV / 4 + 255) / 256, 256>>>(inputs, xbf);

    // 1) xproj = X @ w_x + bias   (M=32768, N=1024, K=256)
    hgemm<<<dim3(NN / 128, TB / 64), 256>>>(xbf, wxT, xproj, bias, VV, NN);

    // 2) full recurrence in ONE persistent kernel (sub-barrier pipelined)
    rnn_persist<<<dim3(16, 8), 128, RNN_SMEM>>>(hbf, whT, xproj, bar);

    // 3+4) fused logits GEMM + log-softmax + weighted NLL -> scalar loss
    logits_loss<<<TB / 64, 256, LL_SMEM>>>(hbf + (size_t)BB * NN, woT, labels, obias, out);
}

// round 11
// speedup vs baseline: 1.0890x; 1.0890x over previous
#include <cuda_runtime.h>
#include <cuda_bf16.h>
#include <math.h>
#include <stdint.h>

// Problem dims (fixed)
#define TT 128
#define BB 256
#define VV 256
#define NN 1024
#define TB (TT*BB)   // 32768

// ---------------------------------------------------------------------------
// Device-global scratch (no allocation allowed in kernel_launch)
__device__ float g_xproj[(size_t)TB * NN];                  // x @ w_x + bias (fp32)
__device__ __nv_bfloat16 g_whT[(size_t)NN * NN];            // w_h^T  bf16 [N=1024,K=1024]
__device__ __nv_bfloat16 g_wxT[(size_t)NN * VV];            // w_x^T  bf16 [N=1024,K=256]
__device__ __nv_bfloat16 g_woT[(size_t)VV * NN];            // w_out^T bf16 [N=256,K=1024]
__device__ __nv_bfloat16 g_xbf[(size_t)TB * VV];            // X bf16 [32768,256]
__device__ __nv_bfloat16 g_hbf[(size_t)(TT + 1) * BB * NN]; // bf16 h states (slice t = h_t)
__device__ unsigned g_bar[TT * 8];                          // per-(step, m-group) barriers

// ===========================================================================
// Helpers
// ===========================================================================
__device__ __forceinline__ void mma16816(
    float& c0, float& c1, float& c2, float& c3,
    uint32_t a0, uint32_t a1, uint32_t a2, uint32_t a3,
    uint32_t b0, uint32_t b1)
{
    asm volatile(
        "mma.sync.aligned.m16n8k16.row.col.f32.bf16.bf16.f32 "
        "{%0,%1,%2,%3}, {%4,%5,%6,%7}, {%8,%9}, {%0,%1,%2,%3};"
        : "+f"(c0), "+f"(c1), "+f"(c2), "+f"(c3)
        : "r"(a0), "r"(a1), "r"(a2), "r"(a3), "r"(b0), "r"(b1));
}

__device__ __forceinline__ void cp16(void* smem_dst, const void* gsrc) {
    uint32_t d;
    asm("{ .reg .u64 t; cvta.to.shared.u64 t, %1; cvt.u32.u64 %0, t; }" : "=r"(d) : "l"(smem_dst));
    asm volatile("cp.async.cg.shared.global [%0], [%1], 16;\n" :: "r"(d), "l"(gsrc));
}
#define CP_COMMIT() asm volatile("cp.async.commit_group;\n" ::: "memory")
#define CP_WAIT(n)  asm volatile("cp.async.wait_group %0;\n" :: "n"(n) : "memory")

__device__ __forceinline__ float tanh_fast(float x) {
    float y;
    asm("tanh.approx.f32 %0, %1;" : "=f"(y) : "f"(x));
    return y;
}

#define PAD 40   // smem row pitch in bf16 for GEMM tiles

// ===========================================================================
// Persistent RNN recurrence kernel (Round-9 structure + fast tanh).
// Grid (16, 8) = 128 CTAs co-resident, 128 threads each.
// CTA (bx,by): rows m0=by*32, cols n0=bx*64.
// Persistent smem: B slice whT[n0:n0+64, :] (132 KB).
// Per step: A tile h_t[m0:m0+32, :1024] (66 KB, 4-chunk pipeline),
//           X tile double-buffered, prefetched one step ahead.
// Barrier: single 16-arrival per (step, m-group of 16 CTAs sharing by).
// ===========================================================================
#define BS_PITCH 1032                      // bf16
#define AS_PITCH 1032                      // bf16
#define XS_PITCH 68                        // fp32
#define SMEM_BS (64 * BS_PITCH * 2)        // 132096
#define SMEM_AS (32 * AS_PITCH * 2)        // 66048
#define SMEM_XS (2 * 32 * XS_PITCH * 4)    // 17408
#define RNN_SMEM (SMEM_BS + SMEM_AS + SMEM_XS)   // 215552

__global__ __launch_bounds__(128, 1) void rnn_persist(
    __nv_bfloat16* __restrict__ hbf,          // (TT+1) slices of [256,1024]
    const __nv_bfloat16* __restrict__ whT,    // [1024,1024]
    const float* __restrict__ xproj,          // [TT,256,1024] fp32
    unsigned* __restrict__ bar)
{
    extern __shared__ char smem_raw[];
    __nv_bfloat16* Bs = (__nv_bfloat16*)smem_raw;                   // [64][1032]
    __nv_bfloat16* As = (__nv_bfloat16*)(smem_raw + SMEM_BS);       // [32][1032]
    float*         Xs = (float*)(smem_raw + SMEM_BS + SMEM_AS);     // [2][32][68]

    const int tid = threadIdx.x;
    const int wid = tid >> 5;
    const int lane = tid & 31;
    const int g  = lane >> 2;    // 0..7
    const int tg = lane & 3;     // 0..3
    const int warpM = wid & 1;   // 2 x 16 rows
    const int warpN = wid >> 1;  // 2 x 32 cols
    const int n0 = blockIdx.x * 64;
    const int m0 = blockIdx.y * 32;
    const int by = blockIdx.y;

    // ---- persistent B slice load: whT rows n0..n0+63, K=1024 ----
    #pragma unroll
    for (int i = 0; i < 64; i++) {
        int u = tid + i * 128;
        int row = u >> 7;        // 0..63
        int seg = u & 127;       // 16B units
        cp16((char*)Bs + row * (BS_PITCH * 2) + seg * 16,
             whT + (size_t)(n0 + row) * NN + seg * 8);
    }
    CP_COMMIT();

    // ---- t = 0: h_1 = tanh(xproj_0) for this (m,n) tile ----
    {
        const float* xp0 = xproj;
        __nv_bfloat16* h1 = hbf + (size_t)1 * BB * NN;
        #pragma unroll
        for (int i = 0; i < 16; i++) {
            int u = tid + i * 128;
            int r = m0 + (u >> 6);
            int cl = n0 + (u & 63);
            h1[(size_t)r * NN + cl] = __float2bfloat16(tanh_fast(xp0[(size_t)r * NN + cl]));
        }
    }
    __threadfence();
    __syncthreads();
    if (tid == 0) {
        atomicAdd(&bar[by], 1u);
        while (*((volatile unsigned*)&bar[by]) < 16u) __nanosleep(32);
    }
    __syncthreads();

    CP_WAIT(0);           // B slice resident; no groups pending
    __syncthreads();

    // prefetch X tile for t=1 into Xs[1]  -> 1 group pending entering the loop
    {
        const float* xp1 = xproj + (size_t)1 * BB * NN;
        float* Xd = Xs + (size_t)(1 & 1) * 32 * XS_PITCH;
        #pragma unroll
        for (int i = 0; i < 4; i++) {
            int u = tid + i * 128;
            int r = u >> 4;
            int sg = u & 15;
            cp16((char*)Xd + r * (XS_PITCH * 4) + sg * 16,
                 xp1 + (size_t)(m0 + r) * NN + n0 + sg * 4);
        }
        CP_COMMIT();
    }

    // ---- steps t = 1 .. 127: h_{t+1} = tanh(xproj_t + h_t @ w_h) ----
    // Invariant entering step t: exactly one cp.async group pending = X(t).
    #pragma unroll 1
    for (int t = 1; t < TT; t++) {
        const __nv_bfloat16* At = hbf + (size_t)t * BB * NN + (size_t)m0 * NN;
        __nv_bfloat16* hn = hbf + (size_t)(t + 1) * BB * NN;

        // A tile: 4 chunks of K=256
        #pragma unroll
        for (int c = 0; c < 4; c++) {
            #pragma unroll
            for (int i = 0; i < 8; i++) {
                int u = tid + i * 128;
                int r = u >> 5;     // 0..31
                int sg = u & 31;    // 32 x 16B per chunk-row
                cp16((char*)As + r * (AS_PITCH * 2) + c * 512 + sg * 16,
                     At + (size_t)r * NN + c * 256 + sg * 8);
            }
            CP_COMMIT();
        }

        // prefetch X for step t+1 (dummy re-fetch of slice t at the last step
        // keeps the pending-group invariant without OOB access)
        {
            const int tn = (t + 1 < TT) ? (t + 1) : t;
            const float* xpn = xproj + (size_t)tn * BB * NN;
            float* Xd = Xs + (size_t)((t + 1) & 1) * 32 * XS_PITCH;
            #pragma unroll
            for (int i = 0; i < 4; i++) {
                int u = tid + i * 128;
                int r = u >> 4;
                int sg = u & 15;
                cp16((char*)Xd + r * (XS_PITCH * 4) + sg * 16,
                     xpn + (size_t)(m0 + r) * NN + n0 + sg * 4);
            }
            CP_COMMIT();
        }
        // pending now: X(t), A0..A3, X(t+1) = 6 groups

        float acc[4][4];
        #pragma unroll
        for (int ni = 0; ni < 4; ni++)
            #pragma unroll
            for (int e = 0; e < 4; e++) acc[ni][e] = 0.0f;

        const int ra = warpM * 16 + g;

#define DO_CHUNK(C, W)                                                          \
        CP_WAIT(W);                                                             \
        __syncthreads();                                                        \
        _Pragma("unroll")                                                       \
        for (int kk = 0; kk < 256; kk += 16) {                                  \
            const int k = (C) * 256 + kk + 2 * tg;                              \
            uint32_t a0 = *(const uint32_t*)&As[(size_t)ra * AS_PITCH + k];     \
            uint32_t a1 = *(const uint32_t*)&As[(size_t)(ra + 8) * AS_PITCH + k];\
            uint32_t a2 = *(const uint32_t*)&As[(size_t)ra * AS_PITCH + k + 8]; \
            uint32_t a3 = *(const uint32_t*)&As[(size_t)(ra + 8) * AS_PITCH + k + 8];\
            _Pragma("unroll")                                                   \
            for (int ni = 0; ni < 4; ni++) {                                    \
                const int bn = warpN * 32 + ni * 8 + g;                         \
                uint32_t b0 = *(const uint32_t*)&Bs[(size_t)bn * BS_PITCH + k]; \
                uint32_t b1 = *(const uint32_t*)&Bs[(size_t)bn * BS_PITCH + k + 8];\
                mma16816(acc[ni][0], acc[ni][1], acc[ni][2], acc[ni][3],        \
                         a0, a1, a2, a3, b0, b1);                               \
            }                                                                   \
        }

        DO_CHUNK(0, 4)    // completes X(t), A0 ; leaves A1,A2,A3,X(t+1)
        DO_CHUNK(1, 3)
        DO_CHUNK(2, 2)
        DO_CHUNK(3, 1)    // leaves only X(t+1) pending
#undef DO_CHUNK

        // epilogue: tanh(acc + Xs[t&1]) -> bf16 h_{t+1}
        const float* Xr = Xs + (size_t)(t & 1) * 32 * XS_PITCH;
        #pragma unroll
        for (int ni = 0; ni < 4; ni++) {
            const int lc = warpN * 32 + ni * 8 + 2 * tg;    // local col 0..63
            #pragma unroll
            for (int h = 0; h < 2; h++) {
                const int lr = warpM * 16 + g + h * 8;      // local row 0..31
                const float2 xv = *(const float2*)&Xr[lr * XS_PITCH + lc];
                float v0 = tanh_fast(acc[ni][2 * h + 0] + xv.x);
                float v1 = tanh_fast(acc[ni][2 * h + 1] + xv.y);
                *(__nv_bfloat162*)(hn + (size_t)(m0 + lr) * NN + n0 + lc) =
                    __floats2bfloat162_rn(v0, v1);
            }
        }

        // per-m-group barrier (16 CTAs sharing by); skip after last step
        if (t < TT - 1) {
            __threadfence();
            __syncthreads();
            if (tid == 0) {
                unsigned* b = &bar[t * 8 + by];
                atomicAdd(b, 1u);
                while (*((volatile unsigned*)b) < 16u) __nanosleep(32);
            }
            __syncthreads();
        }
    }
}

// ===========================================================================
// Generic bf16 HMMA GEMM (xproj only): C[M,N] = A[M,K] @ BT[N,K]^T (+bias).
// CTA 64x128, grid(N/128, M/64). K multiple of 32.
// ===========================================================================
__global__ __launch_bounds__(256) void hgemm(
    const __nv_bfloat16* __restrict__ A,   // [M,K] row-major
    const __nv_bfloat16* __restrict__ BT,  // [N,K] row-major
    float* __restrict__ C,
    const float* __restrict__ bias,        // len N
    int K, int ldc)
{
    __shared__ __nv_bfloat16 As[2][64][PAD];
    __shared__ __nv_bfloat16 Bs[2][128][PAD];

    const int tid = threadIdx.x;
    const int wid = tid >> 5;
    const int lane = tid & 31;
    const int g  = lane >> 2;
    const int tg = lane & 3;
    const int warpM = wid & 1;
    const int warpN = wid >> 1;
    const int n0 = blockIdx.x * 128;
    const int m0 = blockIdx.y * 64;

    const __nv_bfloat16* Ab = A + (size_t)m0 * K;
    const __nv_bfloat16* Bb = BT + (size_t)n0 * K;

    const int ar  = tid >> 2;
    const int seg = tid & 3;

    float acc[2][4][4];
    #pragma unroll
    for (int mi = 0; mi < 2; mi++)
        #pragma unroll
        for (int ni = 0; ni < 4; ni++)
            #pragma unroll
            for (int e = 0; e < 4; e++) acc[mi][ni][e] = 0.0f;

    cp16(&As[0][ar][seg * 8], Ab + (size_t)ar * K + seg * 8);
    #pragma unroll
    for (int i = 0; i < 2; i++)
        cp16(&Bs[0][ar + i * 64][seg * 8], Bb + (size_t)(ar + i * 64) * K + seg * 8);
    CP_COMMIT();

    const int NK = K / 32;
    #pragma unroll 1
    for (int c = 0; c < NK; c++) {
        const int s = c & 1;
        if (c + 1 < NK) {
            const int sn = (c + 1) & 1;
            const int k0 = (c + 1) * 32;
            cp16(&As[sn][ar][seg * 8], Ab + (size_t)ar * K + k0 + seg * 8);
            #pragma unroll
            for (int i = 0; i < 2; i++)
                cp16(&Bs[sn][ar + i * 64][seg * 8],
                     Bb + (size_t)(ar + i * 64) * K + k0 + seg * 8);
            CP_COMMIT();
            CP_WAIT(1);
        } else {
            CP_WAIT(0);
        }
        __syncthreads();

        #pragma unroll
        for (int kk = 0; kk < 32; kk += 16) {
            uint32_t af[2][4];
            #pragma unroll
            for (int mi = 0; mi < 2; mi++) {
                const int r = warpM * 32 + mi * 16 + g;
                af[mi][0] = *(const uint32_t*)&As[s][r][kk + 2 * tg];
                af[mi][1] = *(const uint32_t*)&As[s][r + 8][kk + 2 * tg];
                af[mi][2] = *(const uint32_t*)&As[s][r][kk + 2 * tg + 8];
                af[mi][3] = *(const uint32_t*)&As[s][r + 8][kk + 2 * tg + 8];
            }
            #pragma unroll
            for (int ni = 0; ni < 4; ni++) {
                const int n = warpN * 32 + ni * 8 + g;
                uint32_t b0 = *(const uint32_t*)&Bs[s][n][kk + 2 * tg];
                uint32_t b1 = *(const uint32_t*)&Bs[s][n][kk + 2 * tg + 8];
                #pragma unroll
                for (int mi = 0; mi < 2; mi++)
                    mma16816(acc[mi][ni][0], acc[mi][ni][1], acc[mi][ni][2], acc[mi][ni][3],
                             af[mi][0], af[mi][1], af[mi][2], af[mi][3], b0, b1);
            }
        }
        __syncthreads();
    }

    #pragma unroll
    for (int mi = 0; mi < 2; mi++) {
        const int r0 = m0 + warpM * 32 + mi * 16 + g;
        #pragma unroll
        for (int ni = 0; ni < 4; ni++) {
            const int col = n0 + warpN * 32 + ni * 8 + 2 * tg;
            const float2 bv = *(const float2*)(bias + col);
            #pragma unroll
            for (int h = 0; h < 2; h++) {
                const int r = r0 + h * 8;
                *(float2*)(C + (size_t)r * ldc + col) =
                    make_float2(acc[mi][ni][2 * h + 0] + bv.x,
                                acc[mi][ni][2 * h + 1] + bv.y);
            }
        }
    }
}

// ===========================================================================
// Fused logits + loss kernel.
// C-tile: 64 rows x 256 cols (full V). grid = TB/64 = 512 CTAs, 256 threads.
// ===========================================================================
#define LL_LS_PITCH 264   // fp32 row pitch for staged logits
#define LL_SMEM 67584

__global__ __launch_bounds__(256) void logits_loss(
    const __nv_bfloat16* __restrict__ A,    // h states [TB,1024] bf16
    const __nv_bfloat16* __restrict__ BT,   // woT [256,1024] bf16
    const float* __restrict__ labels,       // [TB,256] fp32
    const float* __restrict__ obias,        // [256]
    float* __restrict__ out)
{
    extern __shared__ char sm[];
    __nv_bfloat16 (*As)[64][PAD] = (__nv_bfloat16 (*)[64][PAD])sm;
    __nv_bfloat16 (*Bs)[256][PAD] = (__nv_bfloat16 (*)[256][PAD])(sm + 2 * 64 * PAD * 2);
    float* Ls = (float*)sm;   // reused after mainloop

    const int tid = threadIdx.x;
    const int wid = tid >> 5;
    const int lane = tid & 31;
    const int g  = lane >> 2;
    const int tg = lane & 3;
    const int warpM = wid & 3;    // 4 x 16 rows
    const int warpN = wid >> 2;   // 2 x 128 cols
    const int m0 = blockIdx.x * 64;

    const __nv_bfloat16* Ab = A + (size_t)m0 * NN;

    const int ar  = tid >> 2;    // 0..63
    const int seg = tid & 3;     // 0..3

    float acc[16][4];
    #pragma unroll
    for (int ni = 0; ni < 16; ni++)
        #pragma unroll
        for (int e = 0; e < 4; e++) acc[ni][e] = 0.0f;

    // prologue chunk 0
    cp16(&(*As)[ar][seg * 8], Ab + (size_t)ar * NN + seg * 8);
    #pragma unroll
    for (int i = 0; i < 4; i++) {
        int u = tid + i * 256;
        int br = u >> 2;
        int bs = u & 3;
        cp16(&(*Bs)[br][bs * 8], BT + (size_t)br * NN + bs * 8);
    }
    CP_COMMIT();

    const int NK = NN / 32;   // 32 chunks
    #pragma unroll 1
    for (int c = 0; c < NK; c++) {
        const int s = c & 1;
        if (c + 1 < NK) {
            const int sn = (c + 1) & 1;
            const int k0 = (c + 1) * 32;
            cp16(&As[sn][0][0] + (size_t)ar * PAD + seg * 8, Ab + (size_t)ar * NN + k0 + seg * 8);
            #pragma unroll
            for (int i = 0; i < 4; i++) {
                int u = tid + i * 256;
                int br = u >> 2;
                int bs = u & 3;
                cp16(&Bs[sn][0][0] + (size_t)br * PAD + bs * 8,
                     BT + (size_t)br * NN + k0 + bs * 8);
            }
            CP_COMMIT();
            CP_WAIT(1);
        } else {
            CP_WAIT(0);
        }
        __syncthreads();

        #pragma unroll
        for (int kk = 0; kk < 32; kk += 16) {
            const int r = warpM * 16 + g;
            uint32_t a0 = *(const uint32_t*)&As[s][r][kk + 2 * tg];
            uint32_t a1 = *(const uint32_t*)&As[s][r + 8][kk + 2 * tg];
            uint32_t a2 = *(const uint32_t*)&As[s][r][kk + 2 * tg + 8];
            uint32_t a3 = *(const uint32_t*)&As[s][r + 8][kk + 2 * tg + 8];
            #pragma unroll
            for (int ni = 0; ni < 16; ni++) {
                const int n = warpN * 128 + ni * 8 + g;
                uint32_t b0 = *(const uint32_t*)&Bs[s][n][kk + 2 * tg];
                uint32_t b1 = *(const uint32_t*)&Bs[s][n][kk + 2 * tg + 8];
                mma16816(acc[ni][0], acc[ni][1], acc[ni][2], acc[ni][3],
                         a0, a1, a2, a3, b0, b1);
            }
        }
        __syncthreads();
    }

    // ---- stage logits (+obias) into smem ----
    #pragma unroll
    for (int ni = 0; ni < 16; ni++) {
        const int col = warpN * 128 + ni * 8 + 2 * tg;
        const float2 bv = *(const float2*)(obias + col);
        #pragma unroll
        for (int h = 0; h < 2; h++) {
            const int row = warpM * 16 + g + h * 8;
            Ls[row * LL_LS_PITCH + col]     = acc[ni][2 * h + 0] + bv.x;
            Ls[row * LL_LS_PITCH + col + 1] = acc[ni][2 * h + 1] + bv.y;
        }
    }
    __syncthreads();

    // ---- per-warp loss over 8 rows each ----
    float wloss = 0.0f;
    #pragma unroll 1
    for (int rr = 0; rr < 8; rr++) {
        const int row = wid * 8 + rr;
        const float* lr = &Ls[row * LL_LS_PITCH];
        const float* labr = labels + (size_t)(m0 + row) * VV;

        float l[8], lb[8];
        #pragma unroll
        for (int j = 0; j < 8; j++) {
            l[j]  = lr[lane + 32 * j];
            lb[j] = labr[lane + 32 * j];
        }
        float m = l[0];
        #pragma unroll
        for (int j = 1; j < 8; j++) m = fmaxf(m, l[j]);
        #pragma unroll
        for (int o = 16; o > 0; o >>= 1) m = fmaxf(m, __shfl_xor_sync(0xffffffffu, m, o));

        float se = 0.0f;
        #pragma unroll
        for (int j = 0; j < 8; j++) se += __expf(l[j] - m);
        #pragma unroll
        for (int o = 16; o > 0; o >>= 1) se += __shfl_xor_sync(0xffffffffu, se, o);
        const float lse = m + __logf(se);

        float cn = 0.0f;
        #pragma unroll
        for (int j = 0; j < 8; j++) cn += lb[j] * (l[j] - lse);
        #pragma unroll
        for (int o = 16; o > 0; o >>= 1) cn += __shfl_xor_sync(0xffffffffu, cn, o);
        wloss += cn;
    }
    if (lane == 0) atomicAdd(out, -wloss * (1.0f / (float)TB));
}

// ---------------------------------------------------------------------------
// Generic fp32 [R,Cc] -> bf16 transpose [Cc,R]
__global__ void transp_bf16(const float* __restrict__ src, __nv_bfloat16* __restrict__ dst,
                            int R, int Cc)
{
    __shared__ float t[32][33];
    const int r0 = blockIdx.x * 32, c0 = blockIdx.y * 32;
    #pragma unroll
    for (int i = 0; i < 32; i += 8)
        t[threadIdx.y + i][threadIdx.x] = src[(size_t)(r0 + threadIdx.y + i) * Cc + c0 + threadIdx.x];
    __syncthreads();
    #pragma unroll
    for (int i = 0; i < 32; i += 8)
        dst[(size_t)(c0 + threadIdx.y + i) * R + r0 + threadIdx.x] =
            __float2bfloat16(t[threadIdx.x][threadIdx.y + i]);
}

// fp32 -> bf16 convert (vectorized; count is a multiple of 4*256)
__global__ __launch_bounds__(256) void f32_to_bf16(
    const float* __restrict__ src, __nv_bfloat16* __restrict__ dst)
{
    const size_t i = (size_t)blockIdx.x * blockDim.x + threadIdx.x;
    float4 v = *(const float4*)(src + i * 4);
    __nv_bfloat162* d = (__nv_bfloat162*)(dst + i * 4);
    d[0] = __floats2bfloat162_rn(v.x, v.y);
    d[1] = __floats2bfloat162_rn(v.z, v.w);
}

__global__ void zero_out(float* out) { if (threadIdx.x == 0) out[0] = 0.0f; }
__global__ void zero_bar(unsigned* bar) {
    int i = blockIdx.x * 256 + threadIdx.x;
    if (i < TT * 8) bar[i] = 0u;
}

// ===========================================================================
extern "C" void kernel_launch(void* const* d_in, const int* in_sizes, int n_in,
                              void* d_out, int out_size)
{
    (void)in_sizes; (void)n_in; (void)out_size;
    const float* inputs  = (const float*)d_in[0]; // [T,B,V] == [TB,V]
    const float* labels  = (const float*)d_in[1]; // [TB,V]
    const float* weights = (const float*)d_in[2]; // [V+N, N]
    const float* bias    = (const float*)d_in[3]; // [N]
    const float* w_out   = (const float*)d_in[4]; // [N,V]
    const float* obias   = (const float*)d_in[5]; // [V]
    float* out = (float*)d_out;

    float *xproj;
    __nv_bfloat16 *whT, *wxT, *woT, *xbf, *hbf;
    unsigned* bar;
    cudaGetSymbolAddress((void**)&xproj,  g_xproj);
    cudaGetSymbolAddress((void**)&whT,    g_whT);
    cudaGetSymbolAddress((void**)&wxT,    g_wxT);
    cudaGetSymbolAddress((void**)&woT,    g_woT);
    cudaGetSymbolAddress((void**)&xbf,    g_xbf);
    cudaGetSymbolAddress((void**)&hbf,    g_hbf);
    cudaGetSymbolAddress((void**)&bar,    g_bar);

    const float* w_x = weights;                    // [V=256, N=1024]
    const float* w_h = weights + (size_t)VV * NN;  // [N=1024, N=1024]

    cudaFuncSetAttribute(rnn_persist, cudaFuncAttributeMaxDynamicSharedMemorySize, RNN_SMEM);
    cudaFuncSetAttribute(logits_loss, cudaFuncAttributeMaxDynamicSharedMemorySize, LL_SMEM);

    zero_out<<<1, 32>>>(out);
    zero_bar<<<4, 256>>>(bar);
    transp_bf16<<<dim3(NN / 32, NN / 32), dim3(32, 8)>>>(w_h, whT, NN, NN);
    transp_bf16<<<dim3(VV / 32, NN / 32), dim3(32, 8)>>>(w_x, wxT, VV, NN);
    transp_bf16<<<dim3(NN / 32, VV / 32), dim3(32, 8)>>>(w_out, woT, NN, VV);
    f32_to_bf16<<<((size_t)TB * VV / 4 + 255) / 256, 256>>>(inputs, xbf);

    // 1) xproj = X @ w_x + bias   (M=32768, N=1024, K=256)
    hgemm<<<dim3(NN / 128, TB / 64), 256>>>(xbf, wxT, xproj, bias, VV, NN);

    // 2) full recurrence in ONE persistent kernel (Round-9 barrier scheme)
    rnn_persist<<<dim3(16, 8), 128, RNN_SMEM>>>(hbf, whT, xproj, bar);

    // 3+4) fused logits GEMM + log-softmax + weighted NLL -> scalar loss
    logits_loss<<<TB / 64, 256, LL_SMEM>>>(hbf + (size_t)BB * NN, woT, labels, obias, out);
}